// round 2
// baseline (speedup 1.0000x reference)
#include <cuda_runtime.h>

#define H_ 128
#define W_ 128
#define HW 16384
#define CIN 384
#define CQ 384
#define C3 1152
#define NH 6
#define HD 64
#define NB 4

// Scratch (no allocation allowed): qkv projection output + attention-sum buffer.
__device__ float g_qkv[(size_t)NB * C3 * HW];   // [b][1152][128][128]  ~302 MB
__device__ float g_attn[(size_t)NB * CQ * HW];  // [b][384][128][128]   ~100 MB

// ---------------------------------------------------------------------------
// SGEMM: C[z] = A(MxK) @ B[z](KxN) + bias (per-row), batched over blockIdx.z.
// mode 0: B = Bext (input x), C = g_qkv
// mode 1: B = g_attn,         C = Cext (final output)
// ---------------------------------------------------------------------------
__global__ __launch_bounds__(256) void sgemm_bias_kernel(
    const float* __restrict__ A, const float* __restrict__ Bext,
    const float* __restrict__ bias, float* __restrict__ Cext,
    int M, int N, int K, int mode)
{
    __shared__ float As[8][128];
    __shared__ float Bs[8][128];

    const float* B = (mode == 0) ? Bext : (const float*)g_attn;
    float*       C = (mode == 0) ? g_qkv : Cext;
    B += (size_t)blockIdx.z * K * N;
    C += (size_t)blockIdx.z * M * N;

    const int tid = threadIdx.x;
    const int tx = tid & 15, ty = tid >> 4;
    const int n0 = blockIdx.x * 128;
    const int m0 = blockIdx.y * 128;

    const int arow  = tid >> 1;
    const int acol4 = (tid & 1) * 4;
    const int brow  = tid >> 5;
    const int bcol  = (tid & 31) * 4;

    float acc[8][8];
    #pragma unroll
    for (int i = 0; i < 8; i++)
        #pragma unroll
        for (int j = 0; j < 8; j++) acc[i][j] = 0.f;

    for (int k0 = 0; k0 < K; k0 += 8) {
        float4 av = *(const float4*)&A[(size_t)(m0 + arow) * K + k0 + acol4];
        As[acol4 + 0][arow] = av.x;
        As[acol4 + 1][arow] = av.y;
        As[acol4 + 2][arow] = av.z;
        As[acol4 + 3][arow] = av.w;
        *(float4*)&Bs[brow][bcol] =
            *(const float4*)&B[(size_t)(k0 + brow) * N + n0 + bcol];
        __syncthreads();

        #pragma unroll
        for (int kk = 0; kk < 8; kk++) {
            float a[8], b[8];
            float4 a0 = *(const float4*)&As[kk][ty * 8];
            float4 a1 = *(const float4*)&As[kk][ty * 8 + 4];
            a[0]=a0.x; a[1]=a0.y; a[2]=a0.z; a[3]=a0.w;
            a[4]=a1.x; a[5]=a1.y; a[6]=a1.z; a[7]=a1.w;
            float4 b0 = *(const float4*)&Bs[kk][tx * 8];
            float4 b1 = *(const float4*)&Bs[kk][tx * 8 + 4];
            b[0]=b0.x; b[1]=b0.y; b[2]=b0.z; b[3]=b0.w;
            b[4]=b1.x; b[5]=b1.y; b[6]=b1.z; b[7]=b1.w;
            #pragma unroll
            for (int i = 0; i < 8; i++)
                #pragma unroll
                for (int j = 0; j < 8; j++)
                    acc[i][j] += a[i] * b[j];
        }
        __syncthreads();
    }

    #pragma unroll
    for (int i = 0; i < 8; i++) {
        float bi = bias[m0 + ty * 8 + i];
        float* crow = &C[(size_t)(m0 + ty * 8 + i) * N + n0 + tx * 8];
        float4 o0, o1;
        o0.x = acc[i][0] + bi; o0.y = acc[i][1] + bi;
        o0.z = acc[i][2] + bi; o0.w = acc[i][3] + bi;
        o1.x = acc[i][4] + bi; o1.y = acc[i][5] + bi;
        o1.z = acc[i][6] + bi; o1.w = acc[i][7] + bi;
        *(float4*)&crow[0] = o0;
        *(float4*)&crow[4] = o1;
    }
}

// ---------------------------------------------------------------------------
// Window MHA: one block per (window, head). 64 tokens, head dim 64.
// SHIFT=0: branch1 (writes g_attn), SHIFT=4: padded branch (accumulates).
// Zero-padded tokens have q=k=v=0 -> keys participate with logit 0 (matches ref).
// smem: q[d][n], k[d][n], v[n][d^swz]; P reuses q's storage as P[j][r]
// (column-disjoint per thread-column, quad converges at shuffles before the
// overwrite). Exactly 48 KB static.
// ---------------------------------------------------------------------------
template <int SHIFT, int NW>
__global__ __launch_bounds__(256) void wattn_kernel()
{
    __shared__ float q_sm[64 * 64];  // [d][n], reused as P[j][r]
    __shared__ float k_sm[64 * 64];  // [d][n]
    __shared__ float v_sm[64 * 64];  // [n][d ^ ((n&15)<<2)]

    const int tid  = threadIdx.x;
    const int widx = blockIdx.x;
    const int head = blockIdx.y;
    const int b    = blockIdx.z;
    const int wy = widx / NW, wx = widx % NW;
    const int y0 = wy * 8 - SHIFT, x0 = wx * 8 - SHIFT;

    const float* base = g_qkv + (size_t)b * C3 * HW;
    const int chq = head * HD;

    #pragma unroll
    for (int it = 0; it < 16; it++) {
        int idx = tid + it * 256;        // idx = d*64 + n
        int d = idx >> 6, n = idx & 63;
        int y = y0 + (n >> 3), x = x0 + (n & 7);
        float qv = 0.f, kv = 0.f, vv = 0.f;
        if (SHIFT == 0 || ((unsigned)y < H_ && (unsigned)x < W_)) {
            size_t poff = (size_t)y * W_ + x;
            qv = base[(size_t)(chq + d) * HW + poff];
            kv = base[(size_t)(CQ + chq + d) * HW + poff];
            vv = base[(size_t)(2 * CQ + chq + d) * HW + poff];
        }
        q_sm[idx] = qv;
        k_sm[idx] = kv;
        v_sm[n * 64 + (d ^ ((n & 15) << 2))] = vv;
    }
    __syncthreads();

    const int r  = tid >> 2;         // query token 0..63
    const int c0 = (tid & 3) * 16;   // key-column block

    float s[16];
    #pragma unroll
    for (int c = 0; c < 16; c++) s[c] = 0.f;
    for (int d = 0; d < 64; d++) {
        float qv = q_sm[d * 64 + r];
        #pragma unroll
        for (int cc = 0; cc < 16; cc += 4) {
            float4 kv = *(const float4*)&k_sm[d * 64 + c0 + cc];
            s[cc + 0] += qv * kv.x; s[cc + 1] += qv * kv.y;
            s[cc + 2] += qv * kv.z; s[cc + 3] += qv * kv.w;
        }
    }

    // row softmax across the 4 quad threads
    float m = s[0];
    #pragma unroll
    for (int c = 1; c < 16; c++) m = fmaxf(m, s[c]);
    m = fmaxf(m, __shfl_xor_sync(0xffffffffu, m, 1));
    m = fmaxf(m, __shfl_xor_sync(0xffffffffu, m, 2));
    const float scale = 0.125f;  // 1/sqrt(64)
    float sum = 0.f;
    #pragma unroll
    for (int c = 0; c < 16; c++) { s[c] = __expf((s[c] - m) * scale); sum += s[c]; }
    sum += __shfl_xor_sync(0xffffffffu, sum, 1);
    sum += __shfl_xor_sync(0xffffffffu, sum, 2);
    float inv = 1.f / sum;

    #pragma unroll
    for (int c = 0; c < 16; c++) q_sm[(c0 + c) * 64 + r] = s[c] * inv;  // P[j][r]
    __syncwarp();

    float o[16];
    #pragma unroll
    for (int c = 0; c < 16; c++) o[c] = 0.f;
    for (int j = 0; j < 64; j++) {
        float p = q_sm[j * 64 + r];
        int swz = (j & 15) << 2;
        #pragma unroll
        for (int cc = 0; cc < 16; cc += 4) {
            float4 vv = *(const float4*)&v_sm[j * 64 + ((c0 + cc) ^ swz)];
            o[cc + 0] += p * vv.x; o[cc + 1] += p * vv.y;
            o[cc + 2] += p * vv.z; o[cc + 3] += p * vv.w;
        }
    }

    int y = y0 + (r >> 3), x = x0 + (r & 7);
    if (SHIFT == 0 || ((unsigned)y < H_ && (unsigned)x < W_)) {
        float* op = g_attn + (size_t)b * CQ * HW + (size_t)(chq + c0) * HW
                           + (size_t)y * W_ + x;
        #pragma unroll
        for (int cc = 0; cc < 16; cc++) {
            if (SHIFT) op[(size_t)cc * HW] += o[cc];
            else       op[(size_t)cc * HW]  = o[cc];
        }
    }
}

// ---------------------------------------------------------------------------
extern "C" void kernel_launch(void* const* d_in, const int* in_sizes, int n_in,
                              void* d_out, int out_size)
{
    (void)in_sizes; (void)n_in; (void)out_size;
    const float* x      = (const float*)d_in[0];
    const float* w_qkv  = (const float*)d_in[1];
    const float* b_qkv  = (const float*)d_in[2];
    const float* w_head = (const float*)d_in[3];
    const float* b_head = (const float*)d_in[4];
    float* out = (float*)d_out;

    // 1) qkv = w_qkv @ x + b_qkv     (M=1152, K=384, N=16384, batch 4)
    {
        dim3 grid(HW / 128, C3 / 128, NB);
        sgemm_bias_kernel<<<grid, 256>>>(w_qkv, x, b_qkv, nullptr,
                                         C3, HW, CIN, 0);
    }
    // 2) branch 1: aligned windows (writes g_attn)
    {
        dim3 grid(16 * 16, NH, NB);
        wattn_kernel<0, 16><<<grid, 256>>>();
    }
    // 3) branch 2: shifted windows with zero-pad (accumulates into g_attn)
    {
        dim3 grid(17 * 17, NH, NB);
        wattn_kernel<4, 17><<<grid, 256>>>();
    }
    // 4) out = w_head @ (x1+x2) + b_head   (M=384, K=384, N=16384, batch 4)
    {
        dim3 grid(HW / 128, CQ / 128, NB);
        sgemm_bias_kernel<<<grid, 256>>>(w_head, nullptr, b_head, out,
                                         CQ, HW, CQ, 1);
    }
}

// round 3
// speedup vs baseline: 1.2689x; 1.2689x over previous
#include <cuda_runtime.h>

#define H_ 128
#define W_ 128
#define HW 16384
#define CIN 384
#define CQ 384
#define C3 1152
#define NH 6
#define HD 64
#define NB 4

// Scratch (no allocation allowed): qkv projection output + attention-sum buffer.
__device__ float g_qkv[(size_t)NB * C3 * HW];   // [b][1152][128][128]  ~302 MB
__device__ float g_attn[(size_t)NB * CQ * HW];  // [b][384][128][128]   ~100 MB

// ---------------------------------------------------------------------------
// SGEMM: C[z] = A(MxK) @ B[z](KxN) + bias (per-row), batched over blockIdx.z.
// 128x128 tile, KTILE=16, register-staged double buffering, 8x8 microtile.
// mode 0: B = Bext (input x), C = g_qkv
// mode 1: B = g_attn,         C = Cext (final output)
// ---------------------------------------------------------------------------
__global__ __launch_bounds__(256, 2) void sgemm_bias_kernel(
    const float* __restrict__ A, const float* __restrict__ Bext,
    const float* __restrict__ bias, float* __restrict__ Cext,
    int M, int N, int K, int mode)
{
    __shared__ float As[2][16][132];   // padded to dodge transpose-store conflicts
    __shared__ float Bs[2][16][128];

    const float* B = (mode == 0) ? Bext : (const float*)g_attn;
    float*       C = (mode == 0) ? g_qkv : Cext;
    B += (size_t)blockIdx.z * K * N;
    C += (size_t)blockIdx.z * M * N;

    const int tid = threadIdx.x;
    const int tx = tid & 15, ty = tid >> 4;
    const int n0 = blockIdx.x * 128;
    const int m0 = blockIdx.y * 128;

    const int arow = tid >> 2;           // 0..63 (and +64)
    const int acol = (tid & 3) * 4;      // 0,4,8,12
    const int brow = tid >> 5;           // 0..7 (and +8)
    const int bcol = (tid & 31) * 4;

    const float* Ap0 = &A[(size_t)(m0 + arow) * K + acol];
    const float* Ap1 = &A[(size_t)(m0 + arow + 64) * K + acol];
    const float* Bp0 = &B[(size_t)brow * N + n0 + bcol];
    const float* Bp1 = &B[(size_t)(brow + 8) * N + n0 + bcol];

    float acc[8][8];
    #pragma unroll
    for (int i = 0; i < 8; i++)
        #pragma unroll
        for (int j = 0; j < 8; j++) acc[i][j] = 0.f;

    const int NS = K / 16;

    // prefetch slice 0
    float4 ra0 = *(const float4*)(Ap0);
    float4 ra1 = *(const float4*)(Ap1);
    float4 rb0 = *(const float4*)(Bp0);
    float4 rb1 = *(const float4*)(Bp1);
    {
        As[0][acol + 0][arow] = ra0.x; As[0][acol + 1][arow] = ra0.y;
        As[0][acol + 2][arow] = ra0.z; As[0][acol + 3][arow] = ra0.w;
        As[0][acol + 0][arow + 64] = ra1.x; As[0][acol + 1][arow + 64] = ra1.y;
        As[0][acol + 2][arow + 64] = ra1.z; As[0][acol + 3][arow + 64] = ra1.w;
        *(float4*)&Bs[0][brow][bcol] = rb0;
        *(float4*)&Bs[0][brow + 8][bcol] = rb1;
    }
    __syncthreads();

    for (int ks = 0; ks < NS; ks++) {
        const int cur = ks & 1;
        if (ks + 1 < NS) {
            const int k0 = (ks + 1) * 16;
            ra0 = *(const float4*)(Ap0 + k0);
            ra1 = *(const float4*)(Ap1 + k0);
            rb0 = *(const float4*)(Bp0 + (size_t)k0 * N);
            rb1 = *(const float4*)(Bp1 + (size_t)k0 * N);
        }

        #pragma unroll
        for (int kk = 0; kk < 16; kk++) {
            float a[8], b[8];
            float4 a0 = *(const float4*)&As[cur][kk][ty * 8];
            float4 a1 = *(const float4*)&As[cur][kk][ty * 8 + 4];
            a[0]=a0.x; a[1]=a0.y; a[2]=a0.z; a[3]=a0.w;
            a[4]=a1.x; a[5]=a1.y; a[6]=a1.z; a[7]=a1.w;
            float4 b0 = *(const float4*)&Bs[cur][kk][tx * 8];
            float4 b1 = *(const float4*)&Bs[cur][kk][tx * 8 + 4];
            b[0]=b0.x; b[1]=b0.y; b[2]=b0.z; b[3]=b0.w;
            b[4]=b1.x; b[5]=b1.y; b[6]=b1.z; b[7]=b1.w;
            #pragma unroll
            for (int i = 0; i < 8; i++)
                #pragma unroll
                for (int j = 0; j < 8; j++)
                    acc[i][j] += a[i] * b[j];
        }

        if (ks + 1 < NS) {
            const int nxt = cur ^ 1;
            As[nxt][acol + 0][arow] = ra0.x; As[nxt][acol + 1][arow] = ra0.y;
            As[nxt][acol + 2][arow] = ra0.z; As[nxt][acol + 3][arow] = ra0.w;
            As[nxt][acol + 0][arow + 64] = ra1.x; As[nxt][acol + 1][arow + 64] = ra1.y;
            As[nxt][acol + 2][arow + 64] = ra1.z; As[nxt][acol + 3][arow + 64] = ra1.w;
            *(float4*)&Bs[nxt][brow][bcol] = rb0;
            *(float4*)&Bs[nxt][brow + 8][bcol] = rb1;
        }
        __syncthreads();
    }

    #pragma unroll
    for (int i = 0; i < 8; i++) {
        float bi = bias[m0 + ty * 8 + i];
        float* crow = &C[(size_t)(m0 + ty * 8 + i) * N + n0 + tx * 8];
        float4 o0, o1;
        o0.x = acc[i][0] + bi; o0.y = acc[i][1] + bi;
        o0.z = acc[i][2] + bi; o0.w = acc[i][3] + bi;
        o1.x = acc[i][4] + bi; o1.y = acc[i][5] + bi;
        o1.z = acc[i][6] + bi; o1.w = acc[i][7] + bi;
        *(float4*)&crow[0] = o0;
        *(float4*)&crow[4] = o1;
    }
}

// ---------------------------------------------------------------------------
// Window MHA v2: one block per (window, head). 64 tokens, head dim 64.
// 4x4 register microtile on a 16x16 thread grid: per d-step one broadcast
// q-float4 + one k-float4 per thread -> ~5x less smem traffic than v1.
// P stored row-major [r][j] in q_sm (after a barrier), PV reads p as float4.
// smem exactly 48 KB static.
// ---------------------------------------------------------------------------
template <int SHIFT, int NW>
__global__ __launch_bounds__(256) void wattn_kernel()
{
    __shared__ float q_sm[64 * 64];  // [d][n]; reused as P[r][j]
    __shared__ float k_sm[64 * 64];  // [d][n]
    __shared__ float v_sm[64 * 64];  // [n][d ^ ((n&15)<<2)]

    const int tid  = threadIdx.x;
    const int widx = blockIdx.x;
    const int head = blockIdx.y;
    const int b    = blockIdx.z;
    const int wy = widx / NW, wx = widx % NW;
    const int y0 = wy * 8 - SHIFT, x0 = wx * 8 - SHIFT;

    const float* base = g_qkv + (size_t)b * C3 * HW;
    const int chq = head * HD;

    #pragma unroll
    for (int it = 0; it < 16; it++) {
        int idx = tid + it * 256;        // idx = d*64 + n
        int d = idx >> 6, n = idx & 63;
        int y = y0 + (n >> 3), x = x0 + (n & 7);
        float qv = 0.f, kv = 0.f, vv = 0.f;
        if (SHIFT == 0 || ((unsigned)y < H_ && (unsigned)x < W_)) {
            size_t poff = (size_t)y * W_ + x;
            qv = base[(size_t)(chq + d) * HW + poff];
            kv = base[(size_t)(CQ + chq + d) * HW + poff];
            vv = base[(size_t)(2 * CQ + chq + d) * HW + poff];
        }
        q_sm[idx] = qv;
        k_sm[idx] = kv;
        v_sm[n * 64 + (d ^ ((n & 15) << 2))] = vv;
    }
    __syncthreads();

    const int tc = tid & 15;         // key / dcol group
    const int tr = tid >> 4;         // query-row group
    const int r0 = tr * 4, c0 = tc * 4;

    // ---- S = Q^T K (4 rows x 4 cols per thread) ----
    float s[4][4];
    #pragma unroll
    for (int i = 0; i < 4; i++)
        #pragma unroll
        for (int j = 0; j < 4; j++) s[i][j] = 0.f;

    for (int d = 0; d < 64; d++) {
        float4 qv = *(const float4*)&q_sm[d * 64 + r0];
        float4 kv = *(const float4*)&k_sm[d * 64 + c0];
        float qa[4] = {qv.x, qv.y, qv.z, qv.w};
        float ka[4] = {kv.x, kv.y, kv.z, kv.w};
        #pragma unroll
        for (int i = 0; i < 4; i++)
            #pragma unroll
            for (int j = 0; j < 4; j++)
                s[i][j] += qa[i] * ka[j];
    }

    // ---- softmax over each row (16 tc lanes hold the 64 cols) ----
    const float scale = 0.125f;  // 1/sqrt(64)
    float inv[4];
    #pragma unroll
    for (int i = 0; i < 4; i++) {
        float m = fmaxf(fmaxf(s[i][0], s[i][1]), fmaxf(s[i][2], s[i][3]));
        m = fmaxf(m, __shfl_xor_sync(0xffffffffu, m, 1));
        m = fmaxf(m, __shfl_xor_sync(0xffffffffu, m, 2));
        m = fmaxf(m, __shfl_xor_sync(0xffffffffu, m, 4));
        m = fmaxf(m, __shfl_xor_sync(0xffffffffu, m, 8));
        float sum = 0.f;
        #pragma unroll
        for (int j = 0; j < 4; j++) {
            s[i][j] = __expf((s[i][j] - m) * scale);
            sum += s[i][j];
        }
        sum += __shfl_xor_sync(0xffffffffu, sum, 1);
        sum += __shfl_xor_sync(0xffffffffu, sum, 2);
        sum += __shfl_xor_sync(0xffffffffu, sum, 4);
        sum += __shfl_xor_sync(0xffffffffu, sum, 8);
        inv[i] = 1.f / sum;
    }

    __syncthreads();  // all QK reads of q_sm complete before P overwrite

    #pragma unroll
    for (int i = 0; i < 4; i++) {
        float4 p4;
        p4.x = s[i][0] * inv[i]; p4.y = s[i][1] * inv[i];
        p4.z = s[i][2] * inv[i]; p4.w = s[i][3] * inv[i];
        *(float4*)&q_sm[(r0 + i) * 64 + c0] = p4;   // P row-major [r][j]
    }
    __syncthreads();

    // ---- O = P V (4 rows x 4 dcols per thread) ----
    float o[4][4];
    #pragma unroll
    for (int i = 0; i < 4; i++)
        #pragma unroll
        for (int j = 0; j < 4; j++) o[i][j] = 0.f;

    for (int j0 = 0; j0 < 64; j0 += 4) {
        float4 p4[4];
        #pragma unroll
        for (int i = 0; i < 4; i++)
            p4[i] = *(const float4*)&q_sm[(r0 + i) * 64 + j0];
        #pragma unroll
        for (int jj = 0; jj < 4; jj++) {
            int j = j0 + jj;
            float4 vv = *(const float4*)&v_sm[j * 64 + (c0 ^ ((j & 15) << 2))];
            float pj[4] = {p4[0].x, p4[1].x, p4[2].x, p4[3].x};
            if (jj == 1) { pj[0]=p4[0].y; pj[1]=p4[1].y; pj[2]=p4[2].y; pj[3]=p4[3].y; }
            if (jj == 2) { pj[0]=p4[0].z; pj[1]=p4[1].z; pj[2]=p4[2].z; pj[3]=p4[3].z; }
            if (jj == 3) { pj[0]=p4[0].w; pj[1]=p4[1].w; pj[2]=p4[2].w; pj[3]=p4[3].w; }
            #pragma unroll
            for (int i = 0; i < 4; i++) {
                o[i][0] += pj[i] * vv.x; o[i][1] += pj[i] * vv.y;
                o[i][2] += pj[i] * vv.z; o[i][3] += pj[i] * vv.w;
            }
        }
    }

    // ---- store / accumulate ----
    #pragma unroll
    for (int i = 0; i < 4; i++) {
        int n = r0 + i;
        int y = y0 + (n >> 3), x = x0 + (n & 7);
        if (SHIFT == 0 || ((unsigned)y < H_ && (unsigned)x < W_)) {
            float* op = g_attn + (size_t)b * CQ * HW
                      + (size_t)(chq + c0) * HW + (size_t)y * W_ + x;
            #pragma unroll
            for (int c = 0; c < 4; c++) {
                if (SHIFT) op[(size_t)c * HW] += o[i][c];
                else       op[(size_t)c * HW]  = o[i][c];
            }
        }
    }
}

// ---------------------------------------------------------------------------
extern "C" void kernel_launch(void* const* d_in, const int* in_sizes, int n_in,
                              void* d_out, int out_size)
{
    (void)in_sizes; (void)n_in; (void)out_size;
    const float* x      = (const float*)d_in[0];
    const float* w_qkv  = (const float*)d_in[1];
    const float* b_qkv  = (const float*)d_in[2];
    const float* w_head = (const float*)d_in[3];
    const float* b_head = (const float*)d_in[4];
    float* out = (float*)d_out;

    // 1) qkv = w_qkv @ x + b_qkv     (M=1152, K=384, N=16384, batch 4)
    {
        dim3 grid(HW / 128, C3 / 128, NB);
        sgemm_bias_kernel<<<grid, 256>>>(w_qkv, x, b_qkv, nullptr,
                                         C3, HW, CIN, 0);
    }
    // 2) branch 1: aligned windows (writes g_attn)
    {
        dim3 grid(16 * 16, NH, NB);
        wattn_kernel<0, 16><<<grid, 256>>>();
    }
    // 3) branch 2: shifted windows with zero-pad (accumulates into g_attn)
    {
        dim3 grid(17 * 17, NH, NB);
        wattn_kernel<4, 17><<<grid, 256>>>();
    }
    // 4) out = w_head @ (x1+x2) + b_head   (M=384, K=384, N=16384, batch 4)
    {
        dim3 grid(HW / 128, CQ / 128, NB);
        sgemm_bias_kernel<<<grid, 256>>>(w_head, nullptr, b_head, out,
                                         CQ, HW, CQ, 1);
    }
}

// round 7
// speedup vs baseline: 2.7160x; 2.1405x over previous
#include <cuda_runtime.h>
#include <cstdint>

#define H_ 128
#define W_ 128
#define HW 16384
#define CIN 384
#define CQ 384
#define C3 1152
#define NH 6
#define HD 64
#define NB 4
#define KDIM 384          // K for both GEMMs
#define NSLAB 12          // 384 / 32

// Scratch (no allocation allowed).
__device__ float g_xT   [(size_t)NB * HW * CIN];  // x transposed  [b][hw][c]
__device__ float g_qkv  [(size_t)NB * C3 * HW];   // qkv           [b][c3][hw]
__device__ float g_attnT[(size_t)NB * HW * CQ];   // attn sum      [b][hw][c]

// ===========================================================================
// mma.sync helpers (baseline PTX, valid for every sm_103 gencode pass)
// ===========================================================================
static __device__ __forceinline__ void mma_bf16(
    float* d, const uint32_t* a, const uint32_t* b)
{
    asm volatile(
        "mma.sync.aligned.m16n8k16.row.col.f32.bf16.bf16.f32 "
        "{%0,%1,%2,%3}, {%4,%5,%6,%7}, {%8,%9}, {%0,%1,%2,%3};"
        : "+f"(d[0]), "+f"(d[1]), "+f"(d[2]), "+f"(d[3])
        : "r"(a[0]), "r"(a[1]), "r"(a[2]), "r"(a[3]),
          "r"(b[0]), "r"(b[1]));
}

static __device__ __forceinline__ void ldm4(uint32_t* r, uint32_t addr)
{
    asm volatile(
        "ldmatrix.sync.aligned.m8n8.x4.shared.b16 {%0,%1,%2,%3}, [%4];"
        : "=r"(r[0]), "=r"(r[1]), "=r"(r[2]), "=r"(r[3])
        : "r"(addr));
}

static __device__ __forceinline__ uint32_t smem_u32(const void* p) {
    uint32_t a;
    asm("{ .reg .u64 t; cvta.to.shared.u64 t, %1; cvt.u32.u64 %0, t; }"
        : "=r"(a) : "l"(p));
    return a;
}

// pack two floats to bf16x2: low half = lo, high half = hi (rn rounding)
static __device__ __forceinline__ uint32_t pack_bf16x2(float lo, float hi) {
    uint32_t r;
    asm("cvt.rn.bf16x2.f32 %0, %1, %2;" : "=r"(r) : "f"(hi), "f"(lo));
    return r;
}
static __device__ __forceinline__ float bf16lo_f(uint32_t r) {
    return __uint_as_float(r << 16);
}
static __device__ __forceinline__ float bf16hi_f(uint32_t r) {
    return __uint_as_float(r & 0xFFFF0000u);
}

// ===========================================================================
// Transpose: x[b][C][HW] -> g_xT[b][HW][C]
// ===========================================================================
__global__ __launch_bounds__(256) void transpose_x_kernel(const float* __restrict__ x)
{
    __shared__ float sm[32][33];
    const int z = blockIdx.z;
    const int hw0 = blockIdx.x * 32, c0 = blockIdx.y * 32;
    const float* xz = x + (size_t)z * CIN * HW;
    float* tz = g_xT + (size_t)z * HW * CIN;
    const int tx = threadIdx.x & 31, ty = threadIdx.x >> 5;

    #pragma unroll
    for (int i = 0; i < 4; i++)
        sm[ty + 8 * i][tx] = xz[(size_t)(c0 + ty + 8 * i) * HW + hw0 + tx];
    __syncthreads();
    #pragma unroll
    for (int i = 0; i < 4; i++)
        tz[(size_t)(hw0 + ty + 8 * i) * CIN + c0 + tx] = sm[tx][ty + 8 * i];
}

// ===========================================================================
// bf16x3-split tensor-core GEMM.
// C[z][M][HW] = A(MxK) @ B[z](HWxK)^T + bias.
// BM=BN=128, BK=32, 8 warps (4m x 2n), warp tile 32x64 (2 x 8 mma tiles).
// Smem rows padded to 80B for conflict-free ldmatrix. Double-buffered slabs,
// register prefetch, one barrier per slab. Epilogue staged via smem.
// mode 0: B = g_xT,    C = g_qkv ; mode 1: B = g_attnT, C = Cext.
// ===========================================================================
#define RSB   80          // bytes per smem row (32 bf16 used + pad)
#define RSW   20          // uint32 per smem row
#define ABUF  10240       // one operand array: 128 rows * 80B
#define SMBUF 40960       // Ahi,Alo,Bhi,Blo
#define GEMM_SMEM (2 * SMBUF)   // 81920; epilogue stage (128*130*4) fits

__global__ __launch_bounds__(256) void gemm_bf16x3_kernel(
    const float* __restrict__ A, const float* __restrict__ bias,
    float* __restrict__ Cext, int mode)
{
    extern __shared__ char dynsm[];
    const uint32_t sbase = smem_u32(dynsm);

    const int tid  = threadIdx.x;
    const int lane = tid & 31;
    const int wid  = tid >> 5;
    const int m0 = blockIdx.x * 128;
    const int n0 = blockIdx.y * 128;
    const int z  = blockIdx.z;

    const float* Bz = ((mode == 0) ? g_xT : g_attnT) + (size_t)z * HW * KDIM;
    float* C = (mode == 0) ? (g_qkv + (size_t)z * C3 * HW)
                           : (Cext  + (size_t)z * CQ * HW);
    const float* Ag = A  + (size_t)m0 * KDIM;
    const float* Bg = Bz + (size_t)n0 * KDIM;

    const int mbase = (wid & 3) * 32;
    const int nbase = (wid >> 2) * 64;

    // ldmatrix lane address patterns
    const int row_a  = (lane & 7) + ((lane >> 3) & 1) * 8;
    const int kboff_a = (lane >> 4) * 16;
    const int row_b  = (lane & 7) + (lane >> 4) * 8;
    const int kboff_b = ((lane >> 3) & 1) * 16;

    float acc[2][8][4];
    #pragma unroll
    for (int i = 0; i < 2; i++)
        #pragma unroll
        for (int j = 0; j < 8; j++)
            #pragma unroll
            for (int r = 0; r < 4; r++) acc[i][j][r] = 0.f;

    // per-thread load coords: idx = tid + i*256; row = idx>>3, k4 = idx&7
    float4 pa[4], pb[4];

    // helper lambda-ish macros for convert+store of one float4
#define CV_STORE(arrHiOff, arrLoOff, rowi, k4i, v) do {                       \
        uint32_t h0 = pack_bf16x2((v).x, (v).y);                              \
        uint32_t h1 = pack_bf16x2((v).z, (v).w);                              \
        float l0 = (v).x - bf16lo_f(h0);                                      \
        float l1 = (v).y - bf16hi_f(h0);                                      \
        float l2 = (v).z - bf16lo_f(h1);                                      \
        float l3 = (v).w - bf16hi_f(h1);                                      \
        uint32_t* hp = (uint32_t*)(dynsm + bufOff + (arrHiOff))               \
                       + (rowi) * RSW + (k4i) * 2;                            \
        uint32_t* lp = (uint32_t*)(dynsm + bufOff + (arrLoOff))               \
                       + (rowi) * RSW + (k4i) * 2;                            \
        hp[0] = h0; hp[1] = h1;                                               \
        lp[0] = pack_bf16x2(l0, l1); lp[1] = pack_bf16x2(l2, l3);             \
    } while (0)

    // ---- prologue: load + store slab 0 ----
    {
        const int bufOff = 0;
        #pragma unroll
        for (int i = 0; i < 4; i++) {
            int idx = tid + i * 256;
            int r = idx >> 3, k4 = idx & 7;
            float4 va = *(const float4*)&Ag[(size_t)r * KDIM + k4 * 4];
            float4 vb = *(const float4*)&Bg[(size_t)r * KDIM + k4 * 4];
            CV_STORE(0, ABUF, r, k4, va);
            CV_STORE(2 * ABUF, 3 * ABUF, r, k4, vb);
        }
    }
    __syncthreads();

    int cur = 0;
    for (int s = 0; s < NSLAB; s++) {
        if (s + 1 < NSLAB) {
            const int k0 = (s + 1) * 32;
            #pragma unroll
            for (int i = 0; i < 4; i++) {
                int idx = tid + i * 256;
                int r = idx >> 3, k4 = idx & 7;
                pa[i] = *(const float4*)&Ag[(size_t)r * KDIM + k0 + k4 * 4];
                pb[i] = *(const float4*)&Bg[(size_t)r * KDIM + k0 + k4 * 4];
            }
        }

        // ---- compute slab s from buffer cur ----
        const uint32_t base = sbase + cur * SMBUF;
        #pragma unroll
        for (int kc = 0; kc < 2; kc++) {
            const int kb = kc * 32;
            uint32_t af[2][4], al[2][4], bf[4][4];
            #pragma unroll
            for (int i = 0; i < 2; i++) {
                uint32_t ra = base + (mbase + i * 16 + row_a) * RSB + kb + kboff_a;
                ldm4(af[i], ra);
                ldm4(al[i], ra + ABUF);
            }
            #pragma unroll
            for (int p = 0; p < 4; p++) {
                uint32_t rb = base + 2 * ABUF
                            + (nbase + p * 16 + row_b) * RSB + kb + kboff_b;
                ldm4(bf[p], rb);
            }
            #pragma unroll
            for (int i = 0; i < 2; i++)
                #pragma unroll
                for (int j = 0; j < 8; j++)
                    mma_bf16(acc[i][j], af[i], &bf[j >> 1][(j & 1) * 2]);
            #pragma unroll
            for (int i = 0; i < 2; i++)
                #pragma unroll
                for (int j = 0; j < 8; j++)
                    mma_bf16(acc[i][j], al[i], &bf[j >> 1][(j & 1) * 2]);
            // B lo
            #pragma unroll
            for (int p = 0; p < 4; p++) {
                uint32_t rb = base + 3 * ABUF
                            + (nbase + p * 16 + row_b) * RSB + kb + kboff_b;
                ldm4(bf[p], rb);
            }
            #pragma unroll
            for (int i = 0; i < 2; i++)
                #pragma unroll
                for (int j = 0; j < 8; j++)
                    mma_bf16(acc[i][j], af[i], &bf[j >> 1][(j & 1) * 2]);
        }

        if (s + 1 < NSLAB) {
            const int bufOff = (cur ^ 1) * SMBUF;
            #pragma unroll
            for (int i = 0; i < 4; i++) {
                int idx = tid + i * 256;
                int r = idx >> 3, k4 = idx & 7;
                CV_STORE(0, ABUF, r, k4, pa[i]);
                CV_STORE(2 * ABUF, 3 * ABUF, r, k4, pb[i]);
            }
        }
        __syncthreads();
        cur ^= 1;
    }

    // ---- epilogue: frags -> smem stage -> coalesced global + bias ----
    float* stage = (float*)dynsm;   // [128][130]
    #pragma unroll
    for (int i = 0; i < 2; i++) {
        #pragma unroll
        for (int j = 0; j < 8; j++) {
            int r = mbase + i * 16 + (lane >> 2);
            int c = nbase + j * 8 + (lane & 3) * 2;
            stage[r * 130 + c]           = acc[i][j][0];
            stage[r * 130 + c + 1]       = acc[i][j][1];
            stage[(r + 8) * 130 + c]     = acc[i][j][2];
            stage[(r + 8) * 130 + c + 1] = acc[i][j][3];
        }
    }
    __syncthreads();

    #pragma unroll
    for (int it = 0; it < 16; it++) {
        const int m = it * 8 + wid;
        const float bi = bias[m0 + m];
        float* crow = &C[(size_t)(m0 + m) * HW + n0];
        #pragma unroll
        for (int jj = 0; jj < 4; jj++) {
            int n = (tid & 31) + jj * 32;
            crow[n] = stage[m * 130 + n] + bi;
        }
    }
#undef CV_STORE
}

// ===========================================================================
// Window MHA (4x4 microtile, 16x16 thread grid; output token-major g_attnT).
// ===========================================================================
template <int SHIFT, int NW>
__global__ __launch_bounds__(256) void wattn_kernel()
{
    __shared__ float q_sm[64 * 64];  // [d][n]; reused as P[r][j]
    __shared__ float k_sm[64 * 64];  // [d][n]
    __shared__ float v_sm[64 * 64];  // [n][d ^ ((n&15)<<2)]

    const int tid  = threadIdx.x;
    const int widx = blockIdx.x;
    const int head = blockIdx.y;
    const int b    = blockIdx.z;
    const int wy = widx / NW, wx = widx % NW;
    const int y0 = wy * 8 - SHIFT, x0 = wx * 8 - SHIFT;

    const float* base = g_qkv + (size_t)b * C3 * HW;
    const int chq = head * HD;

    #pragma unroll
    for (int it = 0; it < 16; it++) {
        int idx = tid + it * 256;        // idx = d*64 + n
        int d = idx >> 6, n = idx & 63;
        int y = y0 + (n >> 3), x = x0 + (n & 7);
        float qv = 0.f, kv = 0.f, vv = 0.f;
        if (SHIFT == 0 || ((unsigned)y < H_ && (unsigned)x < W_)) {
            size_t poff = (size_t)y * W_ + x;
            qv = base[(size_t)(chq + d) * HW + poff];
            kv = base[(size_t)(CQ + chq + d) * HW + poff];
            vv = base[(size_t)(2 * CQ + chq + d) * HW + poff];
        }
        q_sm[idx] = qv;
        k_sm[idx] = kv;
        v_sm[n * 64 + (d ^ ((n & 15) << 2))] = vv;
    }
    __syncthreads();

    const int tc = tid & 15;
    const int tr = tid >> 4;
    const int r0 = tr * 4, c0 = tc * 4;

    float s[4][4];
    #pragma unroll
    for (int i = 0; i < 4; i++)
        #pragma unroll
        for (int j = 0; j < 4; j++) s[i][j] = 0.f;

    for (int d = 0; d < 64; d++) {
        float4 qv = *(const float4*)&q_sm[d * 64 + r0];
        float4 kv = *(const float4*)&k_sm[d * 64 + c0];
        float qa[4] = {qv.x, qv.y, qv.z, qv.w};
        float ka[4] = {kv.x, kv.y, kv.z, kv.w};
        #pragma unroll
        for (int i = 0; i < 4; i++)
            #pragma unroll
            for (int j = 0; j < 4; j++)
                s[i][j] += qa[i] * ka[j];
    }

    const float scale = 0.125f;
    float inv[4];
    #pragma unroll
    for (int i = 0; i < 4; i++) {
        float m = fmaxf(fmaxf(s[i][0], s[i][1]), fmaxf(s[i][2], s[i][3]));
        m = fmaxf(m, __shfl_xor_sync(0xffffffffu, m, 1));
        m = fmaxf(m, __shfl_xor_sync(0xffffffffu, m, 2));
        m = fmaxf(m, __shfl_xor_sync(0xffffffffu, m, 4));
        m = fmaxf(m, __shfl_xor_sync(0xffffffffu, m, 8));
        float sum = 0.f;
        #pragma unroll
        for (int j = 0; j < 4; j++) {
            s[i][j] = __expf((s[i][j] - m) * scale);
            sum += s[i][j];
        }
        sum += __shfl_xor_sync(0xffffffffu, sum, 1);
        sum += __shfl_xor_sync(0xffffffffu, sum, 2);
        sum += __shfl_xor_sync(0xffffffffu, sum, 4);
        sum += __shfl_xor_sync(0xffffffffu, sum, 8);
        inv[i] = 1.f / sum;
    }

    __syncthreads();

    #pragma unroll
    for (int i = 0; i < 4; i++) {
        float4 p4;
        p4.x = s[i][0] * inv[i]; p4.y = s[i][1] * inv[i];
        p4.z = s[i][2] * inv[i]; p4.w = s[i][3] * inv[i];
        *(float4*)&q_sm[(r0 + i) * 64 + c0] = p4;
    }
    __syncthreads();

    float o[4][4];
    #pragma unroll
    for (int i = 0; i < 4; i++)
        #pragma unroll
        for (int j = 0; j < 4; j++) o[i][j] = 0.f;

    for (int j0 = 0; j0 < 64; j0 += 4) {
        float4 p4[4];
        #pragma unroll
        for (int i = 0; i < 4; i++)
            p4[i] = *(const float4*)&q_sm[(r0 + i) * 64 + j0];
        #pragma unroll
        for (int jj = 0; jj < 4; jj++) {
            int j = j0 + jj;
            float4 vv = *(const float4*)&v_sm[j * 64 + (c0 ^ ((j & 15) << 2))];
            float pj[4] = {p4[0].x, p4[1].x, p4[2].x, p4[3].x};
            if (jj == 1) { pj[0]=p4[0].y; pj[1]=p4[1].y; pj[2]=p4[2].y; pj[3]=p4[3].y; }
            if (jj == 2) { pj[0]=p4[0].z; pj[1]=p4[1].z; pj[2]=p4[2].z; pj[3]=p4[3].z; }
            if (jj == 3) { pj[0]=p4[0].w; pj[1]=p4[1].w; pj[2]=p4[2].w; pj[3]=p4[3].w; }
            #pragma unroll
            for (int i = 0; i < 4; i++) {
                o[i][0] += pj[i] * vv.x; o[i][1] += pj[i] * vv.y;
                o[i][2] += pj[i] * vv.z; o[i][3] += pj[i] * vv.w;
            }
        }
    }

    #pragma unroll
    for (int i = 0; i < 4; i++) {
        int n = r0 + i;
        int y = y0 + (n >> 3), x = x0 + (n & 7);
        if (SHIFT == 0 || ((unsigned)y < H_ && (unsigned)x < W_)) {
            float* op = g_attnT + ((size_t)b * HW + (size_t)y * W_ + x) * CQ
                      + chq + c0;
            if (SHIFT) {
                op[0] += o[i][0]; op[1] += o[i][1];
                op[2] += o[i][2]; op[3] += o[i][3];
            } else {
                float4 w4;
                w4.x = o[i][0]; w4.y = o[i][1]; w4.z = o[i][2]; w4.w = o[i][3];
                *(float4*)op = w4;
            }
        }
    }
}

// ---------------------------------------------------------------------------
extern "C" void kernel_launch(void* const* d_in, const int* in_sizes, int n_in,
                              void* d_out, int out_size)
{
    (void)in_sizes; (void)n_in; (void)out_size;
    const float* x      = (const float*)d_in[0];
    const float* w_qkv  = (const float*)d_in[1];
    const float* b_qkv  = (const float*)d_in[2];
    const float* w_head = (const float*)d_in[3];
    const float* b_head = (const float*)d_in[4];
    float* out = (float*)d_out;

    cudaFuncSetAttribute(gemm_bf16x3_kernel,
                         cudaFuncAttributeMaxDynamicSharedMemorySize, GEMM_SMEM);

    // 0) transpose x -> g_xT [b][hw][c]
    {
        dim3 grid(HW / 32, CIN / 32, NB);
        transpose_x_kernel<<<grid, 256>>>(x);
    }
    // 1) qkv = w_qkv @ x + b_qkv  (M=1152)
    {
        dim3 grid(C3 / 128, HW / 128, NB);
        gemm_bf16x3_kernel<<<grid, 256, GEMM_SMEM>>>(w_qkv, b_qkv, nullptr, 0);
    }
    // 2) branch 1: aligned windows (writes g_attnT)
    {
        dim3 grid(16 * 16, NH, NB);
        wattn_kernel<0, 16><<<grid, 256>>>();
    }
    // 3) branch 2: shifted windows with zero-pad (accumulates into g_attnT)
    {
        dim3 grid(17 * 17, NH, NB);
        wattn_kernel<4, 17><<<grid, 256>>>();
    }
    // 4) out = w_head @ (x1+x2) + b_head  (M=384)
    {
        dim3 grid(CQ / 128, HW / 128, NB);
        gemm_bf16x3_kernel<<<grid, 256, GEMM_SMEM>>>(w_head, b_head, out, 1);
    }
}